// round 1
// baseline (speedup 1.0000x reference)
#include <cuda_runtime.h>
#include <stdint.h>

// Problem constants (match reference: NY=NX=512, C=64, N=120000)
#define NXD      512
#define HW       (512 * 512)        // 262144 BEV cells
#define CCH      64                 // channels
#define CELLS4   (HW / 4)           // 65536 threads in gather

// Scratch: inverse map cell -> pillar (or -1). __device__ global = allowed.
__device__ int   g_inv[HW];
// Static zero row; never written, used as load source for empty cells.
__device__ float g_zero[CCH];       // zero-initialized

// ---------------------------------------------------------------------------
// Kernel 1: inv[] = -1   (int4 vectorized, 65536 threads)
// ---------------------------------------------------------------------------
__global__ void k_init_inv() {
    int i = blockIdx.x * blockDim.x + threadIdx.x;   // 0 .. HW/4-1
    if (i < HW / 4) {
        int4 m1 = make_int4(-1, -1, -1, -1);
        reinterpret_cast<int4*>(g_inv)[i] = m1;
    }
}

// ---------------------------------------------------------------------------
// Kernel 2: inv[y*512 + x] = p   (unique indices -> no races matter)
// ---------------------------------------------------------------------------
__global__ void k_scatter_idx(const int* __restrict__ coords, int n) {
    int p = blockIdx.x * blockDim.x + threadIdx.x;
    if (p < n) {
        int y = coords[3 * p + 1];
        int x = coords[3 * p + 2];
        g_inv[y * NXD + x] = p;
    }
}

// ---------------------------------------------------------------------------
// Kernel 3: gather. One thread owns 4 consecutive cells j..j+3.
//   reads : 4 pillar rows, each 256B contiguous (16x LDG.128 / row)
//   writes: for each channel group of 4, one STG.128 per cell-quad, fully
//           coalesced across the warp (consecutive j).
// ---------------------------------------------------------------------------
__global__ void __launch_bounds__(256) k_gather(const float* __restrict__ vf,
                                                float* __restrict__ out) {
    int j4 = blockIdx.x * blockDim.x + threadIdx.x;  // 0 .. CELLS4-1
    if (j4 >= CELLS4) return;
    int j = j4 * 4;

    int p0 = g_inv[j + 0];
    int p1 = g_inv[j + 1];
    int p2 = g_inv[j + 2];
    int p3 = g_inv[j + 3];

    const float4* r0 = (p0 >= 0)
        ? reinterpret_cast<const float4*>(vf + (size_t)p0 * CCH)
        : reinterpret_cast<const float4*>(g_zero);
    const float4* r1 = (p1 >= 0)
        ? reinterpret_cast<const float4*>(vf + (size_t)p1 * CCH)
        : reinterpret_cast<const float4*>(g_zero);
    const float4* r2 = (p2 >= 0)
        ? reinterpret_cast<const float4*>(vf + (size_t)p2 * CCH)
        : reinterpret_cast<const float4*>(g_zero);
    const float4* r3 = (p3 >= 0)
        ? reinterpret_cast<const float4*>(vf + (size_t)p3 * CCH)
        : reinterpret_cast<const float4*>(g_zero);

    float4* out4 = reinterpret_cast<float4*>(out);

    #pragma unroll
    for (int cg = 0; cg < CCH / 4; cg++) {
        float4 a = __ldg(r0 + cg);   // channels 4cg..4cg+3 of pillar p0
        float4 b = __ldg(r1 + cg);
        float4 c = __ldg(r2 + cg);
        float4 d = __ldg(r3 + cg);

        // register transpose: rows = channels, cols = cells
        float4 w0 = make_float4(a.x, b.x, c.x, d.x);  // channel 4cg+0
        float4 w1 = make_float4(a.y, b.y, c.y, d.y);  // channel 4cg+1
        float4 w2 = make_float4(a.z, b.z, c.z, d.z);  // channel 4cg+2
        float4 w3 = make_float4(a.w, b.w, c.w, d.w);  // channel 4cg+3

        // out[(4cg+k)*HW + j .. j+3]  ->  out4[(4cg+k)*(HW/4) + j4]
        out4[(size_t)(4 * cg + 0) * CELLS4 + j4] = w0;
        out4[(size_t)(4 * cg + 1) * CELLS4 + j4] = w1;
        out4[(size_t)(4 * cg + 2) * CELLS4 + j4] = w2;
        out4[(size_t)(4 * cg + 3) * CELLS4 + j4] = w3;
    }
}

// ---------------------------------------------------------------------------
extern "C" void kernel_launch(void* const* d_in, const int* in_sizes, int n_in,
                              void* d_out, int out_size) {
    const float* vf     = (const float*)d_in[0];   // [N, 64] fp32
    const int*   coords = (const int*)d_in[1];     // [N, 3]  int32
    float*       out    = (float*)d_out;           // [64, 262144] fp32

    int n = in_sizes[1] / 3;                       // N = 120000

    // 1) reset inverse map
    k_init_inv<<<(HW / 4 + 255) / 256, 256>>>();
    // 2) scatter pillar ids
    k_scatter_idx<<<(n + 255) / 256, 256>>>(coords, n);
    // 3) gather into canvas (fused zero-fill via g_zero row)
    k_gather<<<(CELLS4 + 255) / 256, 256>>>(vf, out);
}

// round 2
// speedup vs baseline: 1.1080x; 1.1080x over previous
#include <cuda_runtime.h>
#include <stdint.h>

// Problem constants (reference: NY=NX=512, C=64, N=120000)
#define NXD      512
#define HW       (512 * 512)        // 262144 BEV cells
#define CCH      64                 // channels
#define CELLS4   (HW / 4)           // 65536 gather threads
#define NMAX     120000

// Self-validating inverse map (no init pass needed):
//   g_inv[j]  = candidate pillar index for cell j (any historical value is a
//               valid index in [0, N), incl. the zero-initialized state)
//   g_cell[p] = flat cell of pillar p, rewritten every launch
// gather accepts g_inv[j] = p  iff  g_cell[p] == j. Stale entries only pass
// when they are also correct, so output is identical from any prior state.
__device__ int   g_inv[HW];
__device__ int   g_cell[NMAX];
__device__ float g_zero[CCH];       // static zero row for empty cells

// ---------------------------------------------------------------------------
// Kernel 1: scatter pillar ids + record each pillar's cell
// ---------------------------------------------------------------------------
__global__ void k_scatter_idx(const int* __restrict__ coords, int n) {
    int p = blockIdx.x * blockDim.x + threadIdx.x;
    if (p < n) {
        int y = coords[3 * p + 1];
        int x = coords[3 * p + 2];
        int j = y * NXD + x;
        g_inv[j]  = p;
        g_cell[p] = j;
    }
}

// ---------------------------------------------------------------------------
// Kernel 2: gather. One thread owns 4 consecutive cells j..j+3.
//   inv   : one LDG.128 per thread
//   verify: one 4B L2-resident load per cell
//   reads : 4 pillar rows, each 256B contiguous (LDG.128)
//   writes: STG.128, fully coalesced across the warp
// ---------------------------------------------------------------------------
__global__ void __launch_bounds__(256) k_gather(const float* __restrict__ vf,
                                                float* __restrict__ out) {
    int j4 = blockIdx.x * blockDim.x + threadIdx.x;  // 0 .. CELLS4-1
    if (j4 >= CELLS4) return;
    int j = j4 * 4;

    int4 pv = reinterpret_cast<const int4*>(g_inv)[j4];

    bool v0 = (__ldg(&g_cell[pv.x]) == j + 0);
    bool v1 = (__ldg(&g_cell[pv.y]) == j + 1);
    bool v2 = (__ldg(&g_cell[pv.z]) == j + 2);
    bool v3 = (__ldg(&g_cell[pv.w]) == j + 3);

    const float4* r0 = v0 ? reinterpret_cast<const float4*>(vf + (size_t)pv.x * CCH)
                          : reinterpret_cast<const float4*>(g_zero);
    const float4* r1 = v1 ? reinterpret_cast<const float4*>(vf + (size_t)pv.y * CCH)
                          : reinterpret_cast<const float4*>(g_zero);
    const float4* r2 = v2 ? reinterpret_cast<const float4*>(vf + (size_t)pv.z * CCH)
                          : reinterpret_cast<const float4*>(g_zero);
    const float4* r3 = v3 ? reinterpret_cast<const float4*>(vf + (size_t)pv.w * CCH)
                          : reinterpret_cast<const float4*>(g_zero);

    float4* out4 = reinterpret_cast<float4*>(out);

    #pragma unroll
    for (int cg = 0; cg < CCH / 4; cg++) {
        float4 a = __ldg(r0 + cg);   // channels 4cg..4cg+3, cell j+0
        float4 b = __ldg(r1 + cg);
        float4 c = __ldg(r2 + cg);
        float4 d = __ldg(r3 + cg);

        // register transpose: rows = channels, cols = cells
        float4 w0 = make_float4(a.x, b.x, c.x, d.x);
        float4 w1 = make_float4(a.y, b.y, c.y, d.y);
        float4 w2 = make_float4(a.z, b.z, c.z, d.z);
        float4 w3 = make_float4(a.w, b.w, c.w, d.w);

        // out[(4cg+k)*HW + j .. j+3]  ->  out4[(4cg+k)*CELLS4 + j4]
        out4[(size_t)(4 * cg + 0) * CELLS4 + j4] = w0;
        out4[(size_t)(4 * cg + 1) * CELLS4 + j4] = w1;
        out4[(size_t)(4 * cg + 2) * CELLS4 + j4] = w2;
        out4[(size_t)(4 * cg + 3) * CELLS4 + j4] = w3;
    }
}

// ---------------------------------------------------------------------------
extern "C" void kernel_launch(void* const* d_in, const int* in_sizes, int n_in,
                              void* d_out, int out_size) {
    const float* vf     = (const float*)d_in[0];   // [N, 64] fp32
    const int*   coords = (const int*)d_in[1];     // [N, 3]  int32
    float*       out    = (float*)d_out;           // [64, 262144] fp32

    int n = in_sizes[1] / 3;                       // N = 120000

    // 1) scatter pillar ids + per-pillar cell record (self-validating)
    k_scatter_idx<<<(n + 255) / 256, 256>>>(coords, n);
    // 2) gather into canvas (zero-fill fused via g_zero + validity check)
    k_gather<<<(CELLS4 + 255) / 256, 256>>>(vf, out);
}